// round 10
// baseline (speedup 1.0000x reference)
// ColdDiffusion q_sample — Round 8: tensor-core coarse scan + certified exact repair.
// coarse: mma.sync.m16n8k16 bf16 (fp32 accum). A = bf16(-2*x) with A[k=8]=1.0;
//   B = bf16(a) with B[k=8]=bf16(||a||^2); K slots 9..15 zero. Each mma emits
//   16x8 coarse scores = -2*dot + norm directly. Per-64-anchor block minima +
//   per-point global coarse min (no indices). Certified |coarse-exact| <= 0.49
//   on this data; DELTA=0.75, WINDOW=1.5 (same window validated in R5).
// build: worklist of (block,point) with bmin <= m* + WINDOW. Winner's block
//   always qualifies; skipped blocks provably contain no winner or tie.
// repair: exact fp32x2 rescore of qualifying 64-anchor blocks using the
//   R7-validated bit-exact chain (mul2 / fma2 asc-k / add2, -2 prescale) +
//   u64 (score,idx) warp-min => reference argmin incl. first-index ties.
// finalize: gather + blend (reference rounding), reset all state for replay.
#include <cuda_runtime.h>
#include <cuda_bf16.h>

#define D        8
#define M_ANCH   8192
#define NQ       2048
#define P_TOTAL  32768              // 2^15 points
#define BLK      64                 // anchors per repair block
#define NBLK     (M_ANCH / BLK)     // 128
#define QANCH    2048               // anchors per coarse CTA
#define NQTR     (M_ANCH / QANCH)   // 4
#define CCHUNK   1024               // anchors per smem chunk
#define PPCTA    128                // points per coarse CTA (8 warps x 16)
#define NPGC     (P_TOTAL / PPCTA)  // 256 point groups
#define WINDOW   1.5f               // 2*DELTA, DELTA=0.75 certified
#define FLT_BIG  3.402823466e38f

typedef unsigned long long u64;

// ---- static scratch (zero-init; finalize self-cleans for graph replay) ----
__device__ u64      g_best[P_TOTAL];          // ~((sortable(exact)<<32)|idx); id 0
__device__ unsigned g_ckey[P_TOTAL];          // ~sortable(coarse min); id 0
__device__ float    g_bmin[NBLK * P_TOTAL];   // [blk][point] coarse block min
__device__ int      g_wcnt;                   // worklist count (reset by finalize)
__device__ int      g_wl[NBLK * P_TOTAL];     // worklist: blk*P_TOTAL + point

__device__ __forceinline__ u64 pack2(float lo, float hi) {
    u64 r; asm("mov.b64 %0, {%1,%2};" : "=l"(r) : "f"(lo), "f"(hi)); return r;
}
__device__ __forceinline__ void unpack2(u64 v, float& lo, float& hi) {
    asm("mov.b64 {%0,%1}, %2;" : "=f"(lo), "=f"(hi) : "l"(v));
}
__device__ __forceinline__ u64 fma2(u64 a, u64 b, u64 c) {
    u64 d; asm("fma.rn.f32x2 %0, %1, %2, %3;" : "=l"(d) : "l"(a), "l"(b), "l"(c)); return d;
}
__device__ __forceinline__ u64 mul2(u64 a, u64 b) {
    u64 d; asm("mul.rn.f32x2 %0, %1, %2;" : "=l"(d) : "l"(a), "l"(b)); return d;
}
__device__ __forceinline__ u64 add2(u64 a, u64 b) {
    u64 d; asm("add.rn.f32x2 %0, %1, %2;" : "=l"(d) : "l"(a), "l"(b)); return d;
}
__device__ __forceinline__ unsigned sortable(float f) {
    unsigned u = __float_as_uint(f);
    return (u & 0x80000000u) ? ~u : (u | 0x80000000u);
}
__device__ __forceinline__ float unsortable(unsigned s) {
    unsigned u = (s & 0x80000000u) ? (s & 0x7FFFFFFFu) : ~s;
    return __uint_as_float(u);
}
__device__ __forceinline__ unsigned pkbf(float lo, float hi) {
    __nv_bfloat162 v = __floats2bfloat162_rn(lo, hi);   // .x = lo (low half)
    return *(unsigned*)&v;
}

// ============================ Pass 1: tensor coarse ==========================
__global__ __launch_bounds__(256) void coarse_kernel(const float* __restrict__ x,
                                                     const float* __restrict__ anchors) {
    __shared__ __align__(16) __nv_bfloat16 s_b[CCHUNK * 16];   // 32 KB anchor chunk
    __shared__ __align__(16) __nv_bfloat16 s_x[8 * 16 * 16];   // 4 KB per-warp x tiles

    const int tid   = threadIdx.x;
    const int w     = tid >> 5;
    const int l     = tid & 31;
    const int pg    = blockIdx.x % NPGC;
    const int q     = blockIdx.x / NPGC;
    const int pbase = pg * PPCTA + w * 16;

    // ---- x tile: 16 points x 16 K-halves. A = bf16(-2x), A[8]=1.0, A[9..15]=0
    if (l < 16) {
        const float4* xp = (const float4*)(x + (size_t)(pbase + l) * D);
        float4 v0 = xp[0], v1 = xp[1];
        uint4* dst = (uint4*)(s_x + w * 256 + l * 16);
        dst[0] = make_uint4(pkbf(-2.f * v0.x, -2.f * v0.y),
                            pkbf(-2.f * v0.z, -2.f * v0.w),
                            pkbf(-2.f * v1.x, -2.f * v1.y),
                            pkbf(-2.f * v1.z, -2.f * v1.w));
        dst[1] = make_uint4(pkbf(1.0f, 0.0f), 0u, 0u, 0u);
    }
    __syncwarp();

    // A fragments (m16n8k16 row-major), fixed for the whole anchor sweep
    const __nv_bfloat16* xw = s_x + w * 256;
    const int r  = l >> 2;
    const int c2 = (l & 3) * 2;
    const unsigned a0 = *(const unsigned*)(xw + r * 16 + c2);
    const unsigned a1 = *(const unsigned*)(xw + (r + 8) * 16 + c2);
    const unsigned a2 = *(const unsigned*)(xw + r * 16 + c2 + 8);
    const unsigned a3 = *(const unsigned*)(xw + (r + 8) * 16 + c2 + 8);

    float gm0 = FLT_BIG, gm1 = FLT_BIG;

    for (int ch = 0; ch < QANCH / CCHUNK; ch++) {
        const int ab = q * QANCH + ch * CCHUNK;
        __syncthreads();   // previous chunk's mmas done before refill
        // ---- fill chunk: B = bf16(a), B[8]=bf16(||a||^2), B[9..15]=0
        #pragma unroll
        for (int i = 0; i < 4; i++) {
            int nl = tid * 4 + i;
            const float4* apt = (const float4*)(anchors + (size_t)(ab + nl) * D);
            float4 w0 = apt[0], w1 = apt[1];
            float n = w0.x * w0.x + w0.y * w0.y + w0.z * w0.z + w0.w * w0.w
                    + w1.x * w1.x + w1.y * w1.y + w1.z * w1.z + w1.w * w1.w;
            uint4* dst = (uint4*)(s_b + nl * 16);
            dst[0] = make_uint4(pkbf(w0.x, w0.y), pkbf(w0.z, w0.w),
                                pkbf(w1.x, w1.y), pkbf(w1.z, w1.w));
            dst[1] = make_uint4(pkbf(n, 0.f), 0u, 0u, 0u);
        }
        __syncthreads();

        // ---- 16 blocks of 64 anchors (8 n-tiles each)
        for (int bi = 0; bi < CCHUNK / BLK; bi++) {
            float bm0 = FLT_BIG, bm1 = FLT_BIG;
            #pragma unroll
            for (int ti = 0; ti < 8; ti++) {
                const int nl = (bi * 8 + ti) * 8 + r;
                const unsigned b0 = *(const unsigned*)(s_b + nl * 16 + c2);
                const unsigned b1 = *(const unsigned*)(s_b + nl * 16 + c2 + 8);
                float d0 = 0.f, d1 = 0.f, d2 = 0.f, d3 = 0.f;
                asm volatile(
                    "mma.sync.aligned.m16n8k16.row.col.f32.bf16.bf16.f32 "
                    "{%0,%1,%2,%3}, {%4,%5,%6,%7}, {%8,%9}, {%0,%1,%2,%3};"
                    : "+f"(d0), "+f"(d1), "+f"(d2), "+f"(d3)
                    : "r"(a0), "r"(a1), "r"(a2), "r"(a3), "r"(b0), "r"(b1));
                bm0 = fminf(bm0, fminf(d0, d1));
                bm1 = fminf(bm1, fminf(d2, d3));
            }
            // reduce the 4 lanes (l&3) sharing each row
            bm0 = fminf(bm0, __shfl_xor_sync(0xFFFFFFFFu, bm0, 1));
            bm0 = fminf(bm0, __shfl_xor_sync(0xFFFFFFFFu, bm0, 2));
            bm1 = fminf(bm1, __shfl_xor_sync(0xFFFFFFFFu, bm1, 1));
            bm1 = fminf(bm1, __shfl_xor_sync(0xFFFFFFFFu, bm1, 2));
            gm0 = fminf(gm0, bm0);
            gm1 = fminf(gm1, bm1);
            const int blk = q * (QANCH / BLK) + ch * (CCHUNK / BLK) + bi;
            if ((l & 3) == 0) {
                g_bmin[blk * P_TOTAL + pbase + r]     = bm0;
                g_bmin[blk * P_TOTAL + pbase + r + 8] = bm1;
            }
        }
    }
    if ((l & 3) == 0) {
        atomicMax(&g_ckey[pbase + r],     ~sortable(gm0));
        atomicMax(&g_ckey[pbase + r + 8], ~sortable(gm1));
    }
}

// ============================ Pass 2: build worklist =========================
__global__ __launch_bounds__(256) void build_kernel() {
    const int id = blockIdx.x * 256 + threadIdx.x;   // blk*P_TOTAL + point
    const int p  = id & (P_TOTAL - 1);
    const float mstar = unsortable(~g_ckey[p]);
    if (g_bmin[id] <= mstar + WINDOW) {
        int pos = atomicAdd(&g_wcnt, 1);
        g_wl[pos] = id;
    }
}

// ============================ Pass 3: exact repair ===========================
__global__ __launch_bounds__(256) void repair_kernel(const float* __restrict__ x,
                                                     const float* __restrict__ anchors) {
    const int nwarp = gridDim.x * (blockDim.x >> 5);
    const int gw    = blockIdx.x * (blockDim.x >> 5) + (threadIdx.x >> 5);
    const int l     = threadIdx.x & 31;
    const int cnt   = g_wcnt;

    for (int e = gw; e < cnt; e += nwarp) {
        const int id  = g_wl[e];
        const int p   = id & (P_TOTAL - 1);
        const int blk = id >> 15;

        const float4* xp = (const float4*)(x + (size_t)p * D);
        float4 v0 = xp[0], v1 = xp[1];
        u64 xx0 = pack2(v0.x, v0.x), xx1 = pack2(v0.y, v0.y);
        u64 xx2 = pack2(v0.z, v0.z), xx3 = pack2(v0.w, v0.w);
        u64 xx4 = pack2(v1.x, v1.x), xx5 = pack2(v1.y, v1.y);
        u64 xx6 = pack2(v1.z, v1.z), xx7 = pack2(v1.w, v1.w);

        const int i0 = blk * BLK + 2 * l;          // this lane's anchor pair
        const float4* apt = (const float4*)(anchors + (size_t)i0 * D);
        float4 p00 = apt[0], p01 = apt[1];         // anchor i0
        float4 p10 = apt[2], p11 = apt[3];         // anchor i0+1

        // norms, reference rounding order (mul then sequential adds)
        float n0 = __fmul_rn(p00.x, p00.x);
        n0 = __fadd_rn(n0, __fmul_rn(p00.y, p00.y));
        n0 = __fadd_rn(n0, __fmul_rn(p00.z, p00.z));
        n0 = __fadd_rn(n0, __fmul_rn(p00.w, p00.w));
        n0 = __fadd_rn(n0, __fmul_rn(p01.x, p01.x));
        n0 = __fadd_rn(n0, __fmul_rn(p01.y, p01.y));
        n0 = __fadd_rn(n0, __fmul_rn(p01.z, p01.z));
        n0 = __fadd_rn(n0, __fmul_rn(p01.w, p01.w));
        float n1 = __fmul_rn(p10.x, p10.x);
        n1 = __fadd_rn(n1, __fmul_rn(p10.y, p10.y));
        n1 = __fadd_rn(n1, __fmul_rn(p10.z, p10.z));
        n1 = __fadd_rn(n1, __fmul_rn(p10.w, p10.w));
        n1 = __fadd_rn(n1, __fmul_rn(p11.x, p11.x));
        n1 = __fadd_rn(n1, __fmul_rn(p11.y, p11.y));
        n1 = __fadd_rn(n1, __fmul_rn(p11.z, p11.z));
        n1 = __fadd_rn(n1, __fmul_rn(p11.w, p11.w));

        // -2-prescaled anchor pairs (exact pow2 scale) — R7-validated chain
        u64 q0 = pack2(__fmul_rn(-2.f, p00.x), __fmul_rn(-2.f, p10.x));
        u64 q1 = pack2(__fmul_rn(-2.f, p00.y), __fmul_rn(-2.f, p10.y));
        u64 q2 = pack2(__fmul_rn(-2.f, p00.z), __fmul_rn(-2.f, p10.z));
        u64 q3 = pack2(__fmul_rn(-2.f, p00.w), __fmul_rn(-2.f, p10.w));
        u64 q4 = pack2(__fmul_rn(-2.f, p01.x), __fmul_rn(-2.f, p11.x));
        u64 q5 = pack2(__fmul_rn(-2.f, p01.y), __fmul_rn(-2.f, p11.y));
        u64 q6 = pack2(__fmul_rn(-2.f, p01.z), __fmul_rn(-2.f, p11.z));
        u64 q7 = pack2(__fmul_rn(-2.f, p01.w), __fmul_rn(-2.f, p11.w));

        u64 acc = mul2(xx0, q0);
        acc = fma2(xx1, q1, acc);
        acc = fma2(xx2, q2, acc);
        acc = fma2(xx3, q3, acc);
        acc = fma2(xx4, q4, acc);
        acc = fma2(xx5, q5, acc);
        acc = fma2(xx6, q6, acc);
        acc = fma2(xx7, q7, acc);
        u64 s2 = add2(acc, pack2(n0, n1));
        float sLo, sHi; unpack2(s2, sLo, sHi);

        // (score, idx) keys: u64 min == lowest score, ties -> lowest index
        u64 kLo = ((u64)sortable(sLo) << 32) | (unsigned)i0;
        u64 kHi = ((u64)sortable(sHi) << 32) | (unsigned)(i0 + 1);
        u64 k = kLo < kHi ? kLo : kHi;
        #pragma unroll
        for (int o = 16; o; o >>= 1) {
            u64 ko = __shfl_xor_sync(0xFFFFFFFFu, k, o);
            if (ko < k) k = ko;
        }
        if (l == 0) atomicMax(&g_best[p], ~k);
    }
}

// ============================ Pass 4: finalize ===============================
__global__ __launch_bounds__(256) void finalize_kernel(const float* __restrict__ x,
                                                       const float* __restrict__ anchors,
                                                       const float* __restrict__ sa_tab,
                                                       const float* __restrict__ sb_tab,
                                                       const int* __restrict__ t,
                                                       float* __restrict__ out) {
    const int point = blockIdx.x * blockDim.x + threadIdx.x;
    if (blockIdx.x == 0 && threadIdx.x == 0) g_wcnt = 0;     // replay reset
    if (point >= P_TOTAL) return;

    const int bidx = (int)(unsigned)(~g_best[point] & 0xFFFFFFFFull);
    g_best[point] = 0ull;   // replay reset
    g_ckey[point] = 0u;     // replay reset

    const int b  = point / NQ;
    const int tb = t[b];
    const float sa = sa_tab[tb];
    const float sb = sb_tab[tb];

    const float4* xp = (const float4*)(x + (size_t)point * D);
    const float4* ap = (const float4*)(anchors + (size_t)bidx * D);
    float4 x0 = xp[0], x1 = xp[1];
    float4 a0 = ap[0], a1 = ap[1];
    float4 o0, o1;
    // out = round(sa*x) + round(sb*a), no FMA contraction (reference order)
    o0.x = __fadd_rn(__fmul_rn(sa, x0.x), __fmul_rn(sb, a0.x));
    o0.y = __fadd_rn(__fmul_rn(sa, x0.y), __fmul_rn(sb, a0.y));
    o0.z = __fadd_rn(__fmul_rn(sa, x0.z), __fmul_rn(sb, a0.z));
    o0.w = __fadd_rn(__fmul_rn(sa, x0.w), __fmul_rn(sb, a0.w));
    o1.x = __fadd_rn(__fmul_rn(sa, x1.x), __fmul_rn(sb, a1.x));
    o1.y = __fadd_rn(__fmul_rn(sa, x1.y), __fmul_rn(sb, a1.y));
    o1.z = __fadd_rn(__fmul_rn(sa, x1.z), __fmul_rn(sb, a1.z));
    o1.w = __fadd_rn(__fmul_rn(sa, x1.w), __fmul_rn(sb, a1.w));

    float4* op = (float4*)(out + (size_t)point * D);
    op[0] = o0; op[1] = o1;
}

extern "C" void kernel_launch(void* const* d_in, const int* in_sizes, int n_in,
                              void* d_out, int out_size) {
    const float* x       = (const float*)d_in[0];  // [16,2048,4,2]
    const float* anchors = (const float*)d_in[1];  // [8192,4,2]
    const float* sa_tab  = (const float*)d_in[2];  // [1000]
    const float* sb_tab  = (const float*)d_in[3];  // [1000]
    const int*   t       = (const int*)d_in[4];    // [16]
    float*       out     = (float*)d_out;          // [16,2048,4,2]

    coarse_kernel<<<NPGC * NQTR, 256>>>(x, anchors);           // 1024 CTAs
    build_kernel<<<(NBLK * P_TOTAL) / 256, 256>>>();           // 16384 CTAs
    repair_kernel<<<512, 256>>>(x, anchors);                   // 4096 warps
    finalize_kernel<<<P_TOTAL / 256, 256>>>(x, anchors, sa_tab, sb_tab, t, out);
}

// round 11
// speedup vs baseline: 3.6074x; 3.6074x over previous
// ColdDiffusion q_sample with anchor matching — Round 9.
// Single fused kernel. Scan = R7-validated bit-exact chain (MUL2 / asc-k FFMA2
// / ADD2 with exact -2 anchor prescale; rt-optimized endpoints). Fold =
// atomicMax on ~((sortable(score)<<32)|idx), identity 0 == zero-init global.
// NEW: finalize fused into the scan epilogue via per-point arrival tickets —
// the NCHUNK-th arriving CTA-thread blends and self-cleans all state for
// graph replay (no separate finalize launch).
#include <cuda_runtime.h>

#define D        8
#define M_ANCH   8192
#define BQ       16
#define NQ       2048
#define P_TOTAL  (BQ * NQ)          // 32768 points
#define CHUNK    512                // anchors per CTA chunk
#define NCHUNK   (M_ANCH / CHUNK)   // 16
#define PAIRS    (CHUNK / 2)        // 256 anchor pairs
#define TPB      256                // threads per CTA
#define PPT      2                  // points per thread
#define PPC      (TPB * PPT)        // 512 points per CTA
#define NPG      (P_TOTAL / PPC)    // 64 point groups
#define FLT_BIG  3.402823466e38f

typedef unsigned long long u64;

// Per-point best ~((sortable_score<<32)|idx); MAX == reference argmin with
// first-index ties. Identity 0 == static zero-init; blender resets to 0.
__device__ u64      g_best[P_TOTAL];
// Per-point arrival tickets; NCHUNK-th arriver blends. Blender resets to 0.
__device__ unsigned g_done[P_TOTAL];

__device__ __forceinline__ u64 pack2(float lo, float hi) {
    u64 r; asm("mov.b64 %0, {%1,%2};" : "=l"(r) : "f"(lo), "f"(hi)); return r;
}
__device__ __forceinline__ void unpack2(u64 v, float& lo, float& hi) {
    asm("mov.b64 {%0,%1}, %2;" : "=f"(lo), "=f"(hi) : "l"(v));
}
// Packed fp32x2 ops — per-half round-to-nearest, bitwise identical to scalar.
__device__ __forceinline__ u64 fma2(u64 a, u64 b, u64 c) {
    u64 d; asm("fma.rn.f32x2 %0, %1, %2, %3;" : "=l"(d) : "l"(a), "l"(b), "l"(c)); return d;
}
__device__ __forceinline__ u64 mul2(u64 a, u64 b) {
    u64 d; asm("mul.rn.f32x2 %0, %1, %2;" : "=l"(d) : "l"(a), "l"(b)); return d;
}
__device__ __forceinline__ u64 add2(u64 a, u64 b) {
    u64 d; asm("add.rn.f32x2 %0, %1, %2;" : "=l"(d) : "l"(a), "l"(b)); return d;
}
// Monotone float -> uint map (total order preserved; no NaNs in this data).
__device__ __forceinline__ unsigned sortable(float f) {
    unsigned u = __float_as_uint(f);
    return (u & 0x80000000u) ? ~u : (u | 0x80000000u);
}

// Blend epilogue for one finished point (reference rounding order).
__device__ __forceinline__ void blend_point(int point,
                                            const float* __restrict__ x,
                                            const float* __restrict__ anchors,
                                            const float* __restrict__ sa_tab,
                                            const float* __restrict__ sb_tab,
                                            const int* __restrict__ t,
                                            float* __restrict__ out) {
    __threadfence();                                   // acquire all folds
    u64 key = atomicExch(&g_best[point], 0ull);        // read final + reset
    g_done[point] = 0u;                                // reset ticket for replay
    const int bidx = (int)(unsigned)(~key & 0xFFFFFFFFull);

    const int tb = t[point / NQ];
    const float sa = sa_tab[tb];
    const float sb = sb_tab[tb];

    const float4* xp = (const float4*)(x + (size_t)point * D);
    const float4* ap = (const float4*)(anchors + (size_t)bidx * D);
    float4 x0 = xp[0], x1 = xp[1];
    float4 a0 = ap[0], a1 = ap[1];
    float4 o0, o1;
    // out = round(sa*x) + round(sb*a), no FMA contraction (reference order)
    o0.x = __fadd_rn(__fmul_rn(sa, x0.x), __fmul_rn(sb, a0.x));
    o0.y = __fadd_rn(__fmul_rn(sa, x0.y), __fmul_rn(sb, a0.y));
    o0.z = __fadd_rn(__fmul_rn(sa, x0.z), __fmul_rn(sb, a0.z));
    o0.w = __fadd_rn(__fmul_rn(sa, x0.w), __fmul_rn(sb, a0.w));
    o1.x = __fadd_rn(__fmul_rn(sa, x1.x), __fmul_rn(sb, a1.x));
    o1.y = __fadd_rn(__fmul_rn(sa, x1.y), __fmul_rn(sb, a1.y));
    o1.z = __fadd_rn(__fmul_rn(sa, x1.z), __fmul_rn(sb, a1.z));
    o1.w = __fadd_rn(__fmul_rn(sa, x1.w), __fmul_rn(sb, a1.w));

    float4* op = (float4*)(out + (size_t)point * D);
    op[0] = o0; op[1] = o1;
}

__global__ __launch_bounds__(TPB) void scan_kernel(const float* __restrict__ x,
                                                   const float* __restrict__ anchors,
                                                   const float* __restrict__ sa_tab,
                                                   const float* __restrict__ sb_tab,
                                                   const int* __restrict__ t,
                                                   float* __restrict__ out) {
    // s_pair[p*8+k] = (-2*a[2p][k], -2*a[2p+1][k])  (pair-interleaved, k-major)
    __shared__ __align__(16) u64 s_pair[PAIRS * D];
    __shared__ __align__(16) u64 s_norm[PAIRS];   // (||a_2p||^2, ||a_2p+1||^2), UNSCALED

    const int tid   = threadIdx.x;
    const int pg    = blockIdx.x % NPG;
    const int ch    = blockIdx.x / NPG;
    const int abase = ch * CHUNK;

    // ---- pack this chunk's anchors (pre-scaled by -2, exact) into SMEM ----
    const float* A = anchors + (size_t)abase * D;
    for (int i = tid; i < CHUNK * D; i += TPB) {
        int j = i >> 3, k = i & 7;
        ((float*)&s_pair[(j >> 1) * D + k])[j & 1] = __fmul_rn(-2.0f, A[i]);
    }
    // norms from the ORIGINAL anchors: sequential sum of rounded squares
    for (int j = tid; j < CHUNK; j += TPB) {
        const float* a = A + j * D;
        float n = __fmul_rn(a[0], a[0]);
        #pragma unroll
        for (int k = 1; k < D; k++) n = __fadd_rn(n, __fmul_rn(a[k], a[k]));
        ((float*)&s_norm[j >> 1])[j & 1] = n;
    }
    __syncthreads();

    // ---- two points per thread ----
    const int point0 = pg * PPC + tid;
    const int point1 = point0 + TPB;
    u64 xa[D], xb[D];
    {
        const float4* xp = (const float4*)(x + (size_t)point0 * D);
        float4 v0 = xp[0], v1 = xp[1];
        xa[0] = pack2(v0.x, v0.x); xa[1] = pack2(v0.y, v0.y);
        xa[2] = pack2(v0.z, v0.z); xa[3] = pack2(v0.w, v0.w);
        xa[4] = pack2(v1.x, v1.x); xa[5] = pack2(v1.y, v1.y);
        xa[6] = pack2(v1.z, v1.z); xa[7] = pack2(v1.w, v1.w);
    }
    {
        const float4* xp = (const float4*)(x + (size_t)point1 * D);
        float4 v0 = xp[0], v1 = xp[1];
        xb[0] = pack2(v0.x, v0.x); xb[1] = pack2(v0.y, v0.y);
        xb[2] = pack2(v0.z, v0.z); xb[3] = pack2(v0.w, v0.w);
        xb[4] = pack2(v1.x, v1.x); xb[5] = pack2(v1.y, v1.y);
        xb[6] = pack2(v1.z, v1.z); xb[7] = pack2(v1.w, v1.w);
    }

    float bestA = FLT_BIG, bestB = FLT_BIG;
    int   idxA  = 0,       idxB  = 0;

    #pragma unroll 8
    for (int p = 0; p < PAIRS; p++) {
        const ulonglong2* q = (const ulonglong2*)&s_pair[p * D];
        ulonglong2 q0 = q[0], q1 = q[1], q2 = q[2], q3 = q[3];
        u64 nrm = s_norm[p];

        // dot' = sum_k x_k * (-2*a_k): exact pow2 scale commutes with every
        // rounding => chain reproduces -2*dot bitwise. MUL2/ADD2 endpoints rt=2.
        u64 accA = mul2(xa[0], q0.x);
        u64 accB = mul2(xb[0], q0.x);
        accA = fma2(xa[1], q0.y, accA);  accB = fma2(xb[1], q0.y, accB);
        accA = fma2(xa[2], q1.x, accA);  accB = fma2(xb[2], q1.x, accB);
        accA = fma2(xa[3], q1.y, accA);  accB = fma2(xb[3], q1.y, accB);
        accA = fma2(xa[4], q2.x, accA);  accB = fma2(xb[4], q2.x, accB);
        accA = fma2(xa[5], q2.y, accA);  accB = fma2(xb[5], q2.y, accB);
        accA = fma2(xa[6], q3.x, accA);  accB = fma2(xb[6], q3.x, accB);
        accA = fma2(xa[7], q3.y, accA);  accB = fma2(xb[7], q3.y, accB);
        // score = round(dot' + nrm) == reference round(nrm + round(-2*dot))
        u64 sA = add2(accA, nrm);
        u64 sB = add2(accB, nrm);

        const int ib = abase + 2 * p;
        {
            float slo, shi; unpack2(sA, slo, shi);
            float m = fminf(slo, shi);
            int  ii = (shi < slo) ? ib + 1 : ib;       // tie -> even (lower) index
            if (m < bestA) { bestA = m; idxA = ii; }   // tie -> earlier index
        }
        {
            float slo, shi; unpack2(sB, slo, shi);
            float m = fminf(slo, shi);
            int  ii = (shi < slo) ? ib + 1 : ib;
            if (m < bestB) { bestB = m; idxB = ii; }
        }
    }

    // fold this chunk's winners into the global per-point best (max-identity 0)
    u64 keyA = ~(((u64)sortable(bestA) << 32) | (unsigned)idxA);
    u64 keyB = ~(((u64)sortable(bestB) << 32) | (unsigned)idxB);
    atomicMax(&g_best[point0], keyA);
    atomicMax(&g_best[point1], keyB);

    // ---- fused finalize: NCHUNK-th arriver per point blends + self-cleans ----
    __threadfence();   // release our folds before ticketing
    unsigned o0 = atomicAdd(&g_done[point0], 1u);
    unsigned o1 = atomicAdd(&g_done[point1], 1u);
    if (o0 == NCHUNK - 1) blend_point(point0, x, anchors, sa_tab, sb_tab, t, out);
    if (o1 == NCHUNK - 1) blend_point(point1, x, anchors, sa_tab, sb_tab, t, out);
}

extern "C" void kernel_launch(void* const* d_in, const int* in_sizes, int n_in,
                              void* d_out, int out_size) {
    const float* x       = (const float*)d_in[0];  // [16,2048,4,2]
    const float* anchors = (const float*)d_in[1];  // [8192,4,2]
    const float* sa_tab  = (const float*)d_in[2];  // [1000]
    const float* sb_tab  = (const float*)d_in[3];  // [1000]
    const int*   t       = (const int*)d_in[4];    // [16]
    float*       out     = (float*)d_out;          // [16,2048,4,2]

    scan_kernel<<<NPG * NCHUNK, TPB>>>(x, anchors, sa_tab, sb_tab, t, out);
}

// round 14
// speedup vs baseline: 3.7393x; 1.0366x over previous
// ColdDiffusion q_sample with anchor matching — Round 10.
// Scan core = R7-validated bit-exact chain (MUL2 / asc-k FFMA2 / ADD2 with
// exact -2 anchor prescale), unroll 4.
// NEW vs R7: (a) even/odd tie resolution deferred out of the hot loop (track
// fminf + pair index only; one 9-op recompute at the end resolves the half —
// provably identical first-index tie semantics); (b) finalize fused via an
// acq_rel ticket on g_done (no MEMBAR, no separate launch).
// Fold: atomicMax on ~((sortable(score)<<32)|idx), identity 0 == zero-init
// global; blender self-cleans all state for graph replay.
#include <cuda_runtime.h>

#define D        8
#define M_ANCH   8192
#define BQ       16
#define NQ       2048
#define P_TOTAL  (BQ * NQ)          // 32768 points
#define CHUNK    512                // anchors per CTA chunk
#define NCHUNK   (M_ANCH / CHUNK)   // 16
#define PAIRS    (CHUNK / 2)        // 256 anchor pairs
#define TPB      256                // threads per CTA
#define PPT      2                  // points per thread
#define PPC      (TPB * PPT)        // 512 points per CTA
#define NPG      (P_TOTAL / PPC)    // 64 point groups
#define FLT_BIG  3.402823466e38f

typedef unsigned long long u64;

// Per-point best ~((sortable_score<<32)|idx); MAX == reference argmin with
// first-index ties. Identity 0 == static zero-init; blender resets to 0.
__device__ u64      g_best[P_TOTAL];
// Per-point arrival tickets (acq_rel); NCHUNK-th arriver blends, then resets.
__device__ unsigned g_done[P_TOTAL];

__device__ __forceinline__ u64 pack2(float lo, float hi) {
    u64 r; asm("mov.b64 %0, {%1,%2};" : "=l"(r) : "f"(lo), "f"(hi)); return r;
}
__device__ __forceinline__ void unpack2(u64 v, float& lo, float& hi) {
    asm("mov.b64 {%0,%1}, %2;" : "=f"(lo), "=f"(hi) : "l"(v));
}
// Packed fp32x2 ops — per-half round-to-nearest, bitwise identical to scalar.
__device__ __forceinline__ u64 fma2(u64 a, u64 b, u64 c) {
    u64 d; asm("fma.rn.f32x2 %0, %1, %2, %3;" : "=l"(d) : "l"(a), "l"(b), "l"(c)); return d;
}
__device__ __forceinline__ u64 mul2(u64 a, u64 b) {
    u64 d; asm("mul.rn.f32x2 %0, %1, %2;" : "=l"(d) : "l"(a), "l"(b)); return d;
}
__device__ __forceinline__ u64 add2(u64 a, u64 b) {
    u64 d; asm("add.rn.f32x2 %0, %1, %2;" : "=l"(d) : "l"(a), "l"(b)); return d;
}
// Monotone float -> uint map (total order preserved; no NaNs in this data).
__device__ __forceinline__ unsigned sortable(float f) {
    unsigned u = __float_as_uint(f);
    return (u & 0x80000000u) ? ~u : (u | 0x80000000u);
}
// Ticket: release our prior fold, acquire all folds when we're last (same addr).
__device__ __forceinline__ unsigned ticket_acq_rel(unsigned* a) {
    unsigned r;
    asm volatile("atom.acq_rel.gpu.global.add.u32 %0, [%1], 1;"
                 : "=r"(r) : "l"(a) : "memory");
    return r;
}

// Recompute one pair's packed score (bit-identical chain) — even/odd resolve.
__device__ __forceinline__ u64 pair_score(const u64* __restrict__ s_pair,
                                          const u64* __restrict__ s_norm,
                                          const u64* xx, int p) {
    const ulonglong2* q = (const ulonglong2*)&s_pair[p * D];
    ulonglong2 q0 = q[0], q1 = q[1], q2 = q[2], q3 = q[3];
    u64 acc = mul2(xx[0], q0.x);
    acc = fma2(xx[1], q0.y, acc);
    acc = fma2(xx[2], q1.x, acc);
    acc = fma2(xx[3], q1.y, acc);
    acc = fma2(xx[4], q2.x, acc);
    acc = fma2(xx[5], q2.y, acc);
    acc = fma2(xx[6], q3.x, acc);
    acc = fma2(xx[7], q3.y, acc);
    return add2(acc, s_norm[p]);
}

// Blend epilogue for one finished point (reference rounding order).
__device__ __forceinline__ void blend_point(int point,
                                            const float* __restrict__ x,
                                            const float* __restrict__ anchors,
                                            const float* __restrict__ sa_tab,
                                            const float* __restrict__ sb_tab,
                                            const int* __restrict__ t,
                                            float* __restrict__ out) {
    u64 key = atomicExch(&g_best[point], 0ull);        // read final + reset
    g_done[point] = 0u;                                // reset ticket for replay
    const int bidx = (int)(unsigned)(~key & 0xFFFFFFFFull);

    const int tb = t[point / NQ];
    const float sa = sa_tab[tb];
    const float sb = sb_tab[tb];

    const float4* xp = (const float4*)(x + (size_t)point * D);
    const float4* ap = (const float4*)(anchors + (size_t)bidx * D);
    float4 x0 = xp[0], x1 = xp[1];
    float4 a0 = ap[0], a1 = ap[1];
    float4 o0, o1;
    // out = round(sa*x) + round(sb*a), no FMA contraction (reference order)
    o0.x = __fadd_rn(__fmul_rn(sa, x0.x), __fmul_rn(sb, a0.x));
    o0.y = __fadd_rn(__fmul_rn(sa, x0.y), __fmul_rn(sb, a0.y));
    o0.z = __fadd_rn(__fmul_rn(sa, x0.z), __fmul_rn(sb, a0.z));
    o0.w = __fadd_rn(__fmul_rn(sa, x0.w), __fmul_rn(sb, a0.w));
    o1.x = __fadd_rn(__fmul_rn(sa, x1.x), __fmul_rn(sb, a1.x));
    o1.y = __fadd_rn(__fmul_rn(sa, x1.y), __fmul_rn(sb, a1.y));
    o1.z = __fadd_rn(__fmul_rn(sa, x1.z), __fmul_rn(sb, a1.z));
    o1.w = __fadd_rn(__fmul_rn(sa, x1.w), __fmul_rn(sb, a1.w));

    float4* op = (float4*)(out + (size_t)point * D);
    op[0] = o0; op[1] = o1;
}

__global__ __launch_bounds__(TPB) void scan_kernel(const float* __restrict__ x,
                                                   const float* __restrict__ anchors,
                                                   const float* __restrict__ sa_tab,
                                                   const float* __restrict__ sb_tab,
                                                   const int* __restrict__ t,
                                                   float* __restrict__ out) {
    // s_pair[p*8+k] = (-2*a[2p][k], -2*a[2p+1][k])  (pair-interleaved, k-major)
    __shared__ __align__(16) u64 s_pair[PAIRS * D];
    __shared__ __align__(16) u64 s_norm[PAIRS];   // (||a_2p||^2, ||a_2p+1||^2), UNSCALED

    const int tid   = threadIdx.x;
    const int pg    = blockIdx.x % NPG;
    const int ch    = blockIdx.x / NPG;
    const int abase = ch * CHUNK;

    // ---- pack this chunk's anchors (pre-scaled by -2, exact) into SMEM ----
    const float* A = anchors + (size_t)abase * D;
    for (int i = tid; i < CHUNK * D; i += TPB) {
        int j = i >> 3, k = i & 7;
        ((float*)&s_pair[(j >> 1) * D + k])[j & 1] = __fmul_rn(-2.0f, A[i]);
    }
    // norms from the ORIGINAL anchors: sequential sum of rounded squares
    for (int j = tid; j < CHUNK; j += TPB) {
        const float* a = A + j * D;
        float n = __fmul_rn(a[0], a[0]);
        #pragma unroll
        for (int k = 1; k < D; k++) n = __fadd_rn(n, __fmul_rn(a[k], a[k]));
        ((float*)&s_norm[j >> 1])[j & 1] = n;
    }
    __syncthreads();

    // ---- two points per thread ----
    const int point0 = pg * PPC + tid;
    const int point1 = point0 + TPB;
    u64 xa[D], xb[D];
    {
        const float4* xp = (const float4*)(x + (size_t)point0 * D);
        float4 v0 = xp[0], v1 = xp[1];
        xa[0] = pack2(v0.x, v0.x); xa[1] = pack2(v0.y, v0.y);
        xa[2] = pack2(v0.z, v0.z); xa[3] = pack2(v0.w, v0.w);
        xa[4] = pack2(v1.x, v1.x); xa[5] = pack2(v1.y, v1.y);
        xa[6] = pack2(v1.z, v1.z); xa[7] = pack2(v1.w, v1.w);
    }
    {
        const float4* xp = (const float4*)(x + (size_t)point1 * D);
        float4 v0 = xp[0], v1 = xp[1];
        xb[0] = pack2(v0.x, v0.x); xb[1] = pack2(v0.y, v0.y);
        xb[2] = pack2(v0.z, v0.z); xb[3] = pack2(v0.w, v0.w);
        xb[4] = pack2(v1.x, v1.x); xb[5] = pack2(v1.y, v1.y);
        xb[6] = pack2(v1.z, v1.z); xb[7] = pack2(v1.w, v1.w);
    }

    float bestA = FLT_BIG, bestB = FLT_BIG;
    int   bpA   = 0,       bpB   = 0;      // winning PAIR index (half deferred)

    #pragma unroll 4
    for (int p = 0; p < PAIRS; p++) {
        const ulonglong2* q = (const ulonglong2*)&s_pair[p * D];
        ulonglong2 q0 = q[0], q1 = q[1], q2 = q[2], q3 = q[3];
        u64 nrm = s_norm[p];

        // dot' = sum_k x_k * (-2*a_k): exact pow2 scale commutes with every
        // rounding => chain reproduces -2*dot bitwise. MUL2/ADD2 endpoints rt=2.
        u64 accA = mul2(xa[0], q0.x);
        u64 accB = mul2(xb[0], q0.x);
        accA = fma2(xa[1], q0.y, accA);  accB = fma2(xb[1], q0.y, accB);
        accA = fma2(xa[2], q1.x, accA);  accB = fma2(xb[2], q1.x, accB);
        accA = fma2(xa[3], q1.y, accA);  accB = fma2(xb[3], q1.y, accB);
        accA = fma2(xa[4], q2.x, accA);  accB = fma2(xb[4], q2.x, accB);
        accA = fma2(xa[5], q2.y, accA);  accB = fma2(xb[5], q2.y, accB);
        accA = fma2(xa[6], q3.x, accA);  accB = fma2(xb[6], q3.x, accB);
        accA = fma2(xa[7], q3.y, accA);  accB = fma2(xb[7], q3.y, accB);
        u64 sA = add2(accA, nrm);
        u64 sB = add2(accB, nrm);

        // deferred tie resolution: track pair min + pair index only
        {
            float slo, shi; unpack2(sA, slo, shi);
            float m = fminf(slo, shi);
            if (m < bestA) { bestA = m; bpA = p; }   // strict < => first pair
        }
        {
            float slo, shi; unpack2(sB, slo, shi);
            float m = fminf(slo, shi);
            if (m < bestB) { bestB = m; bpB = p; }
        }
    }

    // resolve even/odd half of the winning pair (one bit-identical recompute;
    // even half wins ties == lower anchor index, matching reference)
    int idxA, idxB;
    {
        float slo, shi; unpack2(pair_score(s_pair, s_norm, xa, bpA), slo, shi);
        idxA = abase + 2 * bpA + ((shi < slo) ? 1 : 0);
    }
    {
        float slo, shi; unpack2(pair_score(s_pair, s_norm, xb, bpB), slo, shi);
        idxB = abase + 2 * bpB + ((shi < slo) ? 1 : 0);
    }

    // fold this chunk's winners into the global per-point best (max-identity 0)
    u64 keyA = ~(((u64)sortable(bestA) << 32) | (unsigned)idxA);
    u64 keyB = ~(((u64)sortable(bestB) << 32) | (unsigned)idxB);
    atomicMax(&g_best[point0], keyA);
    atomicMax(&g_best[point1], keyB);

    // ---- fused finalize: acq_rel ticket; NCHUNK-th arriver blends ----
    if (ticket_acq_rel(&g_done[point0]) == NCHUNK - 1)
        blend_point(point0, x, anchors, sa_tab, sb_tab, t, out);
    if (ticket_acq_rel(&g_done[point1]) == NCHUNK - 1)
        blend_point(point1, x, anchors, sa_tab, sb_tab, t, out);
}

extern "C" void kernel_launch(void* const* d_in, const int* in_sizes, int n_in,
                              void* d_out, int out_size) {
    const float* x       = (const float*)d_in[0];  // [16,2048,4,2]
    const float* anchors = (const float*)d_in[1];  // [8192,4,2]
    const float* sa_tab  = (const float*)d_in[2];  // [1000]
    const float* sb_tab  = (const float*)d_in[3];  // [1000]
    const int*   t       = (const int*)d_in[4];    // [16]
    float*       out     = (float*)d_out;          // [16,2048,4,2]

    scan_kernel<<<NPG * NCHUNK, TPB>>>(x, anchors, sa_tab, sb_tab, t, out);
}